// round 1
// baseline (speedup 1.0000x reference)
#include <cuda_runtime.h>

#define HH   48
#define HH2  (48*48)
#define HH3  (48*48*48)
#define NT   256
#define NEG_BIG (-3.402823466e38f)

// Shared workspace (one copy, shared by all template instantiations)
struct Smem {
    float sq[216], sk[216], sv[216];   // pooled q,k,v: [c*27 + token]
    float sc[27*28];                   // scores / weights, padded rows
    float so[216];                     // attention out: [c*27 + token]
    float bias[125];                   // rpb for this head
    float wgt[24];                     // interp fractional weight per out pos
    int   i0[24];                      // interp left index per out pos
};

template<int SW>
__device__ __forceinline__ void load_row_max(const float* __restrict__ p, float& m) {
    if (SW == 8) {
        float4 a = *(const float4*)p;
        float4 b = *(const float4*)(p + 4);
        m = fmaxf(m, fmaxf(fmaxf(fmaxf(a.x, a.y), fmaxf(a.z, a.w)),
                           fmaxf(fmaxf(b.x, b.y), fmaxf(b.z, b.w))));
    } else if (SW == 4) {
        float4 a = *(const float4*)p;
        m = fmaxf(m, fmaxf(fmaxf(a.x, a.y), fmaxf(a.z, a.w)));
    } else if (SW == 2) {
        float2 a = *(const float2*)p;
        m = fmaxf(m, fmaxf(a.x, a.y));
    } else {
        m = fmaxf(m, *p);
    }
}

template<int BW, int SW, int SCALE, int N1>
__device__ __forceinline__ void do_window(
    const float* __restrict__ q, const float* __restrict__ k,
    const float* __restrict__ v, const float* __restrict__ rpb,
    float* __restrict__ out, Smem& sm, int rem)
{
    const int tid = threadIdx.x;
    int wx = rem % N1; rem /= N1;
    int wy = rem % N1; rem /= N1;
    int wz = rem % N1; rem /= N1;
    int head = rem & 1;
    int b    = rem >> 1;
    const int chan_base = b*64 + (SCALE*2 + head)*8;

    // ---- small tables ----
    if (tid < 125) sm.bias[tid] = rpb[tid*2 + head];
    if (tid < BW) {
        float pos = (float)tid * (2.0f / (float)(BW - 1)); // align_corners interp, n_in=3
        int i0 = (pos >= 1.0f) ? 1 : 0;                    // floor clamped to [0,1]
        sm.i0[tid]  = i0;
        sm.wgt[tid] = pos - (float)i0;
    }

    // ---- phase 1: fused max-pool of q,k,v into (27 tokens x 8 ch) ----
    constexpr int G    = (SW == 8) ? 32 : (SW == 4) ? 8 : (SW == 2) ? 4 : 1;
    constexpr int ROWS = (SW * SW) / G;   // x-rows per thread (SW=1 -> 1)
    for (int u = tid; u < 216 * G; u += NT) {
        int p = u / G, g = u - p * G;
        int c  = p / 27, t  = p - c * 27;
        int nz = t / 9,  r2 = t - nz * 9;
        int ny = r2 / 3, nx = r2 - ny * 3;
        int zb = wz*BW + nz*SW;
        int yb = wy*BW + ny*SW;
        int xb = wx*BW + nx*SW;
        float mq = NEG_BIG, mk = NEG_BIG, mv = NEG_BIG;
        #pragma unroll
        for (int rr = 0; rr < ROWS; rr++) {
            int row = g * ROWS + rr;              // in [0, SW*SW)
            int dz = row / SW, dy = row - dz * SW;
            int off = (chan_base + c)*HH3 + (zb + dz)*HH2 + (yb + dy)*HH + xb;
            load_row_max<SW>(q + off, mq);
            load_row_max<SW>(k + off, mk);
            load_row_max<SW>(v + off, mv);
        }
        if (G > 1) {
            #pragma unroll
            for (int o = G >> 1; o > 0; o >>= 1) {
                mq = fmaxf(mq, __shfl_xor_sync(0xffffffffu, mq, o));
                mk = fmaxf(mk, __shfl_xor_sync(0xffffffffu, mk, o));
                mv = fmaxf(mv, __shfl_xor_sync(0xffffffffu, mv, o));
            }
        }
        if (g == 0) { sm.sq[p] = mq; sm.sk[p] = mk; sm.sv[p] = mv; }
    }
    __syncthreads();

    // ---- phase 2: scores = q k^T / sqrt(8) ----
    for (int j = tid; j < 729; j += NT) {
        int m = j / 27, n = j - m * 27;
        float s = 0.f;
        #pragma unroll
        for (int c = 0; c < 8; c++) s += sm.sq[c*27 + m] * sm.sk[c*27 + n];
        sm.sc[m*28 + n] = s * 0.35355339059327373f;
    }
    __syncthreads();

    // ---- phase 3: softmax per row, then ADD bias (post-softmax, per reference) ----
    {
        int wid = tid >> 5, lane = tid & 31;
        for (int m = wid; m < 27; m += NT/32) {
            float x = (lane < 27) ? sm.sc[m*28 + lane] : NEG_BIG;
            float mx = x;
            #pragma unroll
            for (int o = 16; o > 0; o >>= 1) mx = fmaxf(mx, __shfl_xor_sync(0xffffffffu, mx, o));
            float e = (lane < 27) ? __expf(x - mx) : 0.f;
            float s = e;
            #pragma unroll
            for (int o = 16; o > 0; o >>= 1) s += __shfl_xor_sync(0xffffffffu, s, o);
            if (lane < 27) {
                int mz = m / 9,   mr = m - mz*9,   my = mr / 3,  mxc = mr - my*3;
                int nz = lane / 9, nr = lane - nz*9, ny2 = nr / 3, nx2 = nr - ny2*3;
                int bidx = (mz - nz + 2)*25 + (my - ny2 + 2)*5 + (mxc - nx2 + 2);
                sm.sc[m*28 + lane] = e / s + sm.bias[bidx];
            }
        }
    }
    __syncthreads();

    // ---- phase 4: out = w @ v ----
    for (int p = tid; p < 216; p += NT) {
        int c = p / 27, m = p - c * 27;
        float acc = 0.f;
        #pragma unroll
        for (int n = 0; n < 27; n++) acc += sm.sc[m*28 + n] * sm.sv[c*27 + n];
        sm.so[p] = acc;
    }
    __syncthreads();

    // ---- phase 5: trilinear upsample 3^3 -> BW^3 and scatter ----
    constexpr int VEC = (BW % 4 == 0) ? 4 : (BW % 2 == 0) ? 2 : 1;
    constexpr int RX  = BW / VEC;
    for (int u = tid; u < 8*BW*BW*RX; u += NT) {
        int rv   = u % RX;  int rest = u / RX;
        int qq   = rest % BW; rest /= BW;
        int pp   = rest % BW; int c = rest / BW;
        int ip = sm.i0[pp]; float wp = sm.wgt[pp];
        int iq = sm.i0[qq]; float wq = sm.wgt[qq];
        const float* soc = &sm.so[c*27];
        // interpolate over z(pp), y(qq) for the 3 x positions
        float w00 = (1.f - wp) * (1.f - wq);
        float w01 = (1.f - wp) * wq;
        float w10 = wp * (1.f - wq);
        float w11 = wp * wq;
        int b00 = ip*9 + iq*3;
        int b01 = ip*9 + (iq+1)*3;
        int b10 = (ip+1)*9 + iq*3;
        int b11 = (ip+1)*9 + (iq+1)*3;
        float t0 = w00*soc[b00+0] + w01*soc[b01+0] + w10*soc[b10+0] + w11*soc[b11+0];
        float t1 = w00*soc[b00+1] + w01*soc[b01+1] + w10*soc[b10+1] + w11*soc[b11+1];
        float t2 = w00*soc[b00+2] + w01*soc[b01+2] + w10*soc[b10+2] + w11*soc[b11+2];
        float res[4];
        #pragma unroll
        for (int e = 0; e < VEC; e++) {
            int r = rv*VEC + e;
            int ir = sm.i0[r]; float wr = sm.wgt[r];
            float a0 = (ir == 0) ? t0 : t1;
            float a1 = (ir == 0) ? t1 : t2;
            res[e] = (1.f - wr) * a0 + wr * a1;
        }
        int z = wz*BW + pp, y = wy*BW + qq, x = wx*BW + rv*VEC;
        int oidx = (chan_base + c)*HH3 + z*HH2 + y*HH + x;
        if (VEC == 4)      *(float4*)(out + oidx) = make_float4(res[0], res[1], res[2], res[3]);
        else if (VEC == 2) *(float2*)(out + oidx) = make_float2(res[0], res[1]);
        else               out[oidx] = res[0];
    }
}

// Block ranges (heavy scale first so the 64 bw=24 CTAs overlap the whole kernel):
//   [0,64)      scale 3: bw=24 sw=8  N1=2
//   [64,576)    scale 2: bw=12 sw=4  N1=4
//   [576,4672)  scale 1: bw=6  sw=2  N1=8
//   [4672,37440) scale 0: bw=3 sw=1  N1=16
__global__ void __launch_bounds__(NT)
pwa_kernel(const float* __restrict__ q, const float* __restrict__ k,
           const float* __restrict__ v, const float* __restrict__ rpb,
           float* __restrict__ out)
{
    __shared__ Smem sm;
    int bid = blockIdx.x;
    if (bid < 64)        do_window<24, 8, 3, 2 >(q, k, v, rpb, out, sm, bid);
    else if (bid < 576)  do_window<12, 4, 2, 4 >(q, k, v, rpb, out, sm, bid - 64);
    else if (bid < 4672) do_window< 6, 2, 1, 8 >(q, k, v, rpb, out, sm, bid - 576);
    else                 do_window< 3, 1, 0, 16>(q, k, v, rpb, out, sm, bid - 4672);
}

extern "C" void kernel_launch(void* const* d_in, const int* in_sizes, int n_in,
                              void* d_out, int out_size)
{
    const float* q   = (const float*)d_in[0];
    const float* k   = (const float*)d_in[1];
    const float* v   = (const float*)d_in[2];
    const float* rpb = (const float*)d_in[3];
    pwa_kernel<<<37440, NT>>>(q, k, v, rpb, (float*)d_out);
}